// round 3
// baseline (speedup 1.0000x reference)
#include <cuda_runtime.h>
#include <math.h>

#define NB   4
#define HH   128
#define WW   128
#define CC   128
#define GG   8
#define GC   16
#define KK   9
#define NTOK (NB * HH * WW)   // 65536
#define HID  512
#define EPS  1e-5f

// ---------------- scratch (device globals; no allocation allowed) ------------
__device__ float g_xn [NTOK * CC];       // LN1(x)
__device__ float g_xp [NTOK * CC];       // input_proj
__device__ float g_x1 [NTOK * CC];       // gelu(ln(dwconv))
__device__ float g_off[NTOK * GG * KK * 2];
__device__ float g_msk[NTOK * GG * KK];
__device__ float g_y  [NTOK * CC];       // dcn sample output
__device__ float g_x2 [NTOK * CC];       // x + dcn(...)
__device__ float g_h  [NTOK * CC];       // LN2(x2)
__device__ float g_h1 [NTOK * HID];      // gelu(fc1)

__device__ __forceinline__ float gelu_exact(float x) {
    return 0.5f * x * (1.0f + erff(x * 0.70710678118654752f));
}

// ---------------- LayerNorm over C=128, one token per block -----------------
__global__ __launch_bounds__(128) void ln_kernel(
    const float* __restrict__ in, const float* __restrict__ g,
    const float* __restrict__ b, float* __restrict__ out)
{
    const int tok = blockIdx.x;
    const int c   = threadIdx.x;
    float v = in[(size_t)tok * CC + c];

    float s = v, s2 = v * v;
    #pragma unroll
    for (int o = 16; o > 0; o >>= 1) {
        s  += __shfl_xor_sync(0xffffffffu, s,  o);
        s2 += __shfl_xor_sync(0xffffffffu, s2, o);
    }
    __shared__ float ws[4], ws2[4];
    const int wid = c >> 5, lid = c & 31;
    if (lid == 0) { ws[wid] = s; ws2[wid] = s2; }
    __syncthreads();
    s  = ws[0] + ws[1] + ws[2] + ws[3];
    s2 = ws2[0] + ws2[1] + ws2[2] + ws2[3];
    const float mean = s * (1.0f / CC);
    const float var  = s2 * (1.0f / CC) - mean * mean;
    const float rstd = rsqrtf(var + EPS);
    out[(size_t)tok * CC + c] = (v - mean) * rstd * g[c] + b[c];
}

// ------- depthwise 3x3 conv (on xn) + bias, then LN + GELU, per token -------
__global__ __launch_bounds__(128) void dwconv_ln_gelu_kernel(
    const float* __restrict__ xn, const float* __restrict__ dwk,
    const float* __restrict__ dwb, const float* __restrict__ lg,
    const float* __restrict__ lb, float* __restrict__ out)
{
    const int tok = blockIdx.x;
    const int c   = threadIdx.x;
    const int n = tok / (HH * WW);
    const int hw = tok % (HH * WW);
    const int h = hw / WW, w = hw % WW;

    float acc = dwb[c];
    #pragma unroll
    for (int ky = 0; ky < 3; ky++) {
        const int yy = h + ky - 1;
        if (yy < 0 || yy >= HH) continue;
        #pragma unroll
        for (int kx = 0; kx < 3; kx++) {
            const int xx = w + kx - 1;
            if (xx < 0 || xx >= WW) continue;
            acc += xn[(((size_t)n * HH + yy) * WW + xx) * CC + c]
                 * dwk[(ky * 3 + kx) * CC + c];
        }
    }

    float s = acc, s2 = acc * acc;
    #pragma unroll
    for (int o = 16; o > 0; o >>= 1) {
        s  += __shfl_xor_sync(0xffffffffu, s,  o);
        s2 += __shfl_xor_sync(0xffffffffu, s2, o);
    }
    __shared__ float ws[4], ws2[4];
    const int wid = c >> 5, lid = c & 31;
    if (lid == 0) { ws[wid] = s; ws2[wid] = s2; }
    __syncthreads();
    s  = ws[0] + ws[1] + ws[2] + ws[3];
    s2 = ws2[0] + ws2[1] + ws2[2] + ws2[3];
    const float mean = s * (1.0f / CC);
    const float var  = s2 * (1.0f / CC) - mean * mean;
    const float rstd = rsqrtf(var + EPS);
    const float v = (acc - mean) * rstd * lg[c] + lb[c];
    out[(size_t)tok * CC + c] = gelu_exact(v);
}

// ---------------- generic SGEMM: C = act(A@B + bias) [+ res] ----------------
__global__ __launch_bounds__(256) void sgemm_kernel(
    const float* __restrict__ A, const float* __restrict__ B,
    const float* __restrict__ bias, const float* __restrict__ res,
    float* __restrict__ C, int M, int N, int K, int act)
{
    const int BM = 64, BN = 64, BK = 16, TM = 4, TN = 4;
    __shared__ float As[BK][BM];
    __shared__ float Bs[BK][BN + 1];

    const int brow = blockIdx.y * BM;
    const int bcol = blockIdx.x * BN;
    const int tid  = threadIdx.x;
    const int tr   = tid >> 4;
    const int tc   = tid & 15;

    float acc[TM][TN];
    #pragma unroll
    for (int i = 0; i < TM; i++)
        #pragma unroll
        for (int j = 0; j < TN; j++) acc[i][j] = 0.0f;

    for (int k0 = 0; k0 < K; k0 += BK) {
        #pragma unroll
        for (int i = tid; i < BM * BK; i += 256) {
            const int r = i >> 4, cl = i & 15;
            As[cl][r] = A[(size_t)(brow + r) * K + (k0 + cl)];
        }
        #pragma unroll
        for (int i = tid; i < BK * BN; i += 256) {
            const int r = i >> 6, cl = i & 63;
            const int gc = bcol + cl;
            Bs[r][cl] = (gc < N) ? B[(size_t)(k0 + r) * N + gc] : 0.0f;
        }
        __syncthreads();
        #pragma unroll
        for (int kk = 0; kk < BK; kk++) {
            float a[TM], b[TN];
            #pragma unroll
            for (int i = 0; i < TM; i++) a[i] = As[kk][tr * TM + i];
            #pragma unroll
            for (int j = 0; j < TN; j++) b[j] = Bs[kk][tc * TN + j];
            #pragma unroll
            for (int i = 0; i < TM; i++)
                #pragma unroll
                for (int j = 0; j < TN; j++)
                    acc[i][j] = fmaf(a[i], b[j], acc[i][j]);
        }
        __syncthreads();
    }

    #pragma unroll
    for (int i = 0; i < TM; i++) {
        const int r = brow + tr * TM + i;
        #pragma unroll
        for (int j = 0; j < TN; j++) {
            const int cidx = bcol + tc * TN + j;
            if (cidx < N) {
                float v = acc[i][j] + bias[cidx];
                if (act == 1) v = gelu_exact(v);
                if (res) v += res[(size_t)r * N + cidx];
                C[(size_t)r * N + cidx] = v;
            }
        }
    }
}

// ---------------- softmax over K=9, per (token, group) ----------------------
__global__ __launch_bounds__(256) void softmax_kernel(float* __restrict__ m)
{
    const int idx = blockIdx.x * blockDim.x + threadIdx.x;
    if (idx >= NTOK * GG) return;
    float* p = m + (size_t)idx * KK;
    float v[KK], mx = -1e30f;
    #pragma unroll
    for (int k = 0; k < KK; k++) { v[k] = p[k]; mx = fmaxf(mx, v[k]); }
    float s = 0.0f;
    #pragma unroll
    for (int k = 0; k < KK; k++) { v[k] = __expf(v[k] - mx); s += v[k]; }
    const float inv = 1.0f / s;
    #pragma unroll
    for (int k = 0; k < KK; k++) p[k] = v[k] * inv;
}

// ---------------- deformable sampling, one token per block ------------------
__global__ __launch_bounds__(128) void dcn_sample_kernel(
    const float* __restrict__ xp, const float* __restrict__ off,
    const float* __restrict__ msk, float* __restrict__ y)
{
    const int tok = blockIdx.x;
    const int n  = tok / (HH * WW);
    const int hw = tok % (HH * WW);
    const int h = hw / WW, w = hw % WW;
    const int g  = threadIdx.x >> 4;
    const int cc = threadIdx.x & 15;

    __shared__ float s_off[GG * KK * 2];   // 144
    __shared__ float s_msk[GG * KK];       // 72
    // FIX R1: 144 > blockDim (128); must loop, not a single guarded store.
    for (int i = threadIdx.x; i < GG * KK * 2; i += 128)
        s_off[i] = off[(size_t)tok * (GG * KK * 2) + i];
    for (int i = threadIdx.x; i < GG * KK; i += 128)
        s_msk[i] = msk[(size_t)tok * (GG * KK) + i];
    __syncthreads();

    const float* base = xp + ((size_t)n * HH * WW) * CC + g * GC + cc;
    float acc = 0.0f;

    #pragma unroll
    for (int k = 0; k < KK; k++) {
        const float ox = s_off[(g * KK + k) * 2 + 0];
        const float oy = s_off[(g * KK + k) * 2 + 1];
        const float mw = s_msk[g * KK + k];
        const float px = (float)(w + 1 + (k / 3) - 1) + ox;
        const float py = (float)(h + 1 + (k % 3) - 1) + oy;
        const float x0f = floorf(px), y0f = floorf(py);
        const float tx = px - x0f, ty = py - y0f;
        const int x0 = (int)x0f, y0 = (int)y0f;

        float v00 = 0.f, v01 = 0.f, v10 = 0.f, v11 = 0.f;
        const bool yi0 = (y0 >= 1) & (y0 <= HH);
        const bool yi1 = (y0 + 1 >= 1) & (y0 + 1 <= HH);
        const bool xi0 = (x0 >= 1) & (x0 <= WW);
        const bool xi1 = (x0 + 1 >= 1) & (x0 + 1 <= WW);
        if (yi0 & xi0) v00 = base[((size_t)(y0 - 1) * WW + (x0 - 1)) * CC];
        if (yi0 & xi1) v01 = base[((size_t)(y0 - 1) * WW + (x0    )) * CC];
        if (yi1 & xi0) v10 = base[((size_t)(y0    ) * WW + (x0 - 1)) * CC];
        if (yi1 & xi1) v11 = base[((size_t)(y0    ) * WW + (x0    )) * CC];

        const float bl = (1.f - ty) * (1.f - tx) * v00 + (1.f - ty) * tx * v01
                       + ty * (1.f - tx) * v10 + ty * tx * v11;
        acc = fmaf(mw, bl, acc);
    }
    y[(size_t)tok * CC + g * GC + cc] = acc;
}

// ---------------------------------------------------------------------------
extern "C" void kernel_launch(void* const* d_in, const int* in_sizes, int n_in,
                              void* d_out, int out_size)
{
    const float* x      = (const float*)d_in[0];
    const float* ln1_g  = (const float*)d_in[1];
    const float* ln1_b  = (const float*)d_in[2];
    const float* in_w   = (const float*)d_in[3];
    const float* in_b   = (const float*)d_in[4];
    const float* dw_k   = (const float*)d_in[5];
    const float* dw_b   = (const float*)d_in[6];
    const float* dwln_g = (const float*)d_in[7];
    const float* dwln_b = (const float*)d_in[8];
    const float* off_w  = (const float*)d_in[9];
    const float* off_b  = (const float*)d_in[10];
    const float* mask_w = (const float*)d_in[11];
    const float* mask_b = (const float*)d_in[12];
    const float* out_w  = (const float*)d_in[13];
    const float* out_b  = (const float*)d_in[14];
    const float* ln2_g  = (const float*)d_in[15];
    const float* ln2_b  = (const float*)d_in[16];
    const float* fc1_w  = (const float*)d_in[17];
    const float* fc1_b  = (const float*)d_in[18];
    const float* fc2_w  = (const float*)d_in[19];
    const float* fc2_b  = (const float*)d_in[20];
    float* out = (float*)d_out;

    float *xn, *xp, *x1, *offp, *mskp, *yp, *x2, *hp, *h1;
    cudaGetSymbolAddress((void**)&xn,   g_xn);
    cudaGetSymbolAddress((void**)&xp,   g_xp);
    cudaGetSymbolAddress((void**)&x1,   g_x1);
    cudaGetSymbolAddress((void**)&offp, g_off);
    cudaGetSymbolAddress((void**)&mskp, g_msk);
    cudaGetSymbolAddress((void**)&yp,   g_y);
    cudaGetSymbolAddress((void**)&x2,   g_x2);
    cudaGetSymbolAddress((void**)&hp,   g_h);
    cudaGetSymbolAddress((void**)&h1,   g_h1);

    const dim3 gemm128(CC / 64, NTOK / 64);
    const dim3 gemm144(3, NTOK / 64);
    const dim3 gemm72(2, NTOK / 64);
    const dim3 gemm512(HID / 64, NTOK / 64);

    ln_kernel<<<NTOK, 128>>>(x, ln1_g, ln1_b, xn);
    sgemm_kernel<<<gemm128, 256>>>(xn, in_w, in_b, nullptr, xp, NTOK, CC, CC, 0);
    dwconv_ln_gelu_kernel<<<NTOK, 128>>>(xn, dw_k, dw_b, dwln_g, dwln_b, x1);
    sgemm_kernel<<<gemm144, 256>>>(x1, off_w, off_b, nullptr, offp, NTOK, GG * KK * 2, CC, 0);
    sgemm_kernel<<<gemm72, 256>>>(x1, mask_w, mask_b, nullptr, mskp, NTOK, GG * KK, CC, 0);
    softmax_kernel<<<(NTOK * GG + 255) / 256, 256>>>(mskp);
    dcn_sample_kernel<<<NTOK, 128>>>(xp, offp, mskp, yp);
    sgemm_kernel<<<gemm128, 256>>>(yp, out_w, out_b, x, x2, NTOK, CC, CC, 0);
    ln_kernel<<<NTOK, 128>>>(x2, ln2_g, ln2_b, hp);
    sgemm_kernel<<<gemm512, 256>>>(hp, fc1_w, fc1_b, nullptr, h1, NTOK, HID, CC, 1);
    sgemm_kernel<<<gemm128, 256>>>(h1, fc2_w, fc2_b, x2, out, NTOK, CC, HID, 0);
}

// round 4
// speedup vs baseline: 2.2402x; 2.2402x over previous
#include <cuda_runtime.h>
#include <math.h>
#include <stdint.h>

#define NB   4
#define HH   128
#define WW   128
#define CC   128
#define GG   8
#define GC   16
#define KK   9
#define NTOK (NB * HH * WW)   // 65536
#define HID  512
#define EPS  1e-5f

// ---------------- scratch (device globals; no allocation allowed) ------------
__device__ float g_xn [NTOK * CC];       // LN1(x)
__device__ float g_xp [NTOK * CC];       // input_proj
__device__ float g_x1 [NTOK * CC];       // gelu(ln(dwconv))
__device__ float g_off[NTOK * GG * KK * 2];
__device__ float g_msk[NTOK * GG * KK];  // mask LOGITS (softmax fused into sampler)
__device__ float g_y  [NTOK * CC];       // dcn sample output
__device__ float g_x2 [NTOK * CC];       // x + dcn(...)
__device__ float g_h  [NTOK * CC];       // LN2(x2)
__device__ float g_h1 [NTOK * HID];      // gelu(fc1)

__device__ __forceinline__ float gelu_exact(float x) {
    return 0.5f * x * (1.0f + erff(x * 0.70710678118654752f));
}

__device__ __forceinline__ float to_tf32(float x) {
    uint32_t u;
    asm("cvt.rna.tf32.f32 %0, %1;" : "=r"(u) : "f"(x));
    return __uint_as_float(u);
}

__device__ __forceinline__ void mma_tf32(float c[4], const uint32_t a[4], const uint32_t b[2]) {
    asm volatile(
        "mma.sync.aligned.m16n8k8.row.col.f32.tf32.tf32.f32 "
        "{%0,%1,%2,%3}, {%4,%5,%6,%7}, {%8,%9}, {%0,%1,%2,%3};"
        : "+f"(c[0]), "+f"(c[1]), "+f"(c[2]), "+f"(c[3])
        : "r"(a[0]), "r"(a[1]), "r"(a[2]), "r"(a[3]), "r"(b[0]), "r"(b[1]));
}

// ---------------- LayerNorm over C=128, one token per block -----------------
__global__ __launch_bounds__(128) void ln_kernel(
    const float* __restrict__ in, const float* __restrict__ g,
    const float* __restrict__ b, float* __restrict__ out)
{
    const int tok = blockIdx.x;
    const int c   = threadIdx.x;
    float v = in[(size_t)tok * CC + c];

    float s = v, s2 = v * v;
    #pragma unroll
    for (int o = 16; o > 0; o >>= 1) {
        s  += __shfl_xor_sync(0xffffffffu, s,  o);
        s2 += __shfl_xor_sync(0xffffffffu, s2, o);
    }
    __shared__ float ws[4], ws2[4];
    const int wid = c >> 5, lid = c & 31;
    if (lid == 0) { ws[wid] = s; ws2[wid] = s2; }
    __syncthreads();
    s  = ws[0] + ws[1] + ws[2] + ws[3];
    s2 = ws2[0] + ws2[1] + ws2[2] + ws2[3];
    const float mean = s * (1.0f / CC);
    const float var  = s2 * (1.0f / CC) - mean * mean;
    const float rstd = rsqrtf(var + EPS);
    out[(size_t)tok * CC + c] = (v - mean) * rstd * g[c] + b[c];
}

// ------- depthwise 3x3 conv (on xn) + bias, then LN + GELU, per token -------
__global__ __launch_bounds__(128) void dwconv_ln_gelu_kernel(
    const float* __restrict__ xn, const float* __restrict__ dwk,
    const float* __restrict__ dwb, const float* __restrict__ lg,
    const float* __restrict__ lb, float* __restrict__ out)
{
    const int tok = blockIdx.x;
    const int c   = threadIdx.x;
    const int n = tok / (HH * WW);
    const int hw = tok % (HH * WW);
    const int h = hw / WW, w = hw % WW;

    float acc = dwb[c];
    #pragma unroll
    for (int ky = 0; ky < 3; ky++) {
        const int yy = h + ky - 1;
        if (yy < 0 || yy >= HH) continue;
        #pragma unroll
        for (int kx = 0; kx < 3; kx++) {
            const int xx = w + kx - 1;
            if (xx < 0 || xx >= WW) continue;
            acc += xn[(((size_t)n * HH + yy) * WW + xx) * CC + c]
                 * dwk[(ky * 3 + kx) * CC + c];
        }
    }

    float s = acc, s2 = acc * acc;
    #pragma unroll
    for (int o = 16; o > 0; o >>= 1) {
        s  += __shfl_xor_sync(0xffffffffu, s,  o);
        s2 += __shfl_xor_sync(0xffffffffu, s2, o);
    }
    __shared__ float ws[4], ws2[4];
    const int wid = c >> 5, lid = c & 31;
    if (lid == 0) { ws[wid] = s; ws2[wid] = s2; }
    __syncthreads();
    s  = ws[0] + ws[1] + ws[2] + ws[3];
    s2 = ws2[0] + ws2[1] + ws2[2] + ws2[3];
    const float mean = s * (1.0f / CC);
    const float var  = s2 * (1.0f / CC) - mean * mean;
    const float rstd = rsqrtf(var + EPS);
    const float v = (acc - mean) * rstd * lg[c] + lb[c];
    out[(size_t)tok * CC + c] = gelu_exact(v);
}

// -------- tf32 tensor-core GEMM: C = act(A@B + bias) [+ res] ----------------
// A: MxK row-major (M mult of 128, K mult of 32), B: KxN row-major.
// BM=128, BN=64, BK=32; 256 thr = 8 warps (4 along M x 2 along N);
// warp tile 32x32 = 2x4 m16n8k8 mma tiles.
__global__ __launch_bounds__(256) void gemm_tf32_kernel(
    const float* __restrict__ A, const float* __restrict__ B,
    const float* __restrict__ bias, const float* __restrict__ res,
    float* __restrict__ C, int M, int N, int K, int act)
{
    __shared__ float As[128][36];   // [m][k], stride 36 (odd-mult-of-4 pad)
    __shared__ float Bs[64][36];    // [n][k] (transposed), stride 36

    const int tid   = threadIdx.x;
    const int warp  = tid >> 5;
    const int lane  = tid & 31;
    const int grp   = lane >> 2;      // 0..7
    const int t4    = lane & 3;       // 0..3
    const int wm    = warp & 3;       // 0..3 (M)
    const int wn    = warp >> 2;      // 0..1 (N)
    const int brow  = blockIdx.y * 128;
    const int bcol  = blockIdx.x * 64;

    float acc[2][4][4];
    #pragma unroll
    for (int i = 0; i < 2; i++)
        #pragma unroll
        for (int j = 0; j < 4; j++)
            #pragma unroll
            for (int q = 0; q < 4; q++) acc[i][j][q] = 0.0f;

    for (int k0 = 0; k0 < K; k0 += 32) {
        // load A tile 128x32 as float4 (1024 f4 / 256 thr = 4 each)
        #pragma unroll
        for (int it = 0; it < 4; it++) {
            const int idx = it * 256 + tid;
            const int r = idx >> 3, fc = idx & 7;
            float4 v = *(const float4*)&A[(size_t)(brow + r) * K + k0 + fc * 4];
            float4 w = make_float4(to_tf32(v.x), to_tf32(v.y), to_tf32(v.z), to_tf32(v.w));
            *(float4*)&As[r][fc * 4] = w;
        }
        // load B tile 32x64, store transposed [n][k]
        #pragma unroll
        for (int it = 0; it < 2; it++) {
            const int idx = it * 256 + tid;
            const int kr = idx >> 4, fc = idx & 15;
            const int n = bcol + fc * 4;
            float4 v = make_float4(0.f, 0.f, 0.f, 0.f);
            if (n < N) v = *(const float4*)&B[(size_t)(k0 + kr) * N + n];
            Bs[fc * 4 + 0][kr] = to_tf32(v.x);
            Bs[fc * 4 + 1][kr] = to_tf32(v.y);
            Bs[fc * 4 + 2][kr] = to_tf32(v.z);
            Bs[fc * 4 + 3][kr] = to_tf32(v.w);
        }
        __syncthreads();

        #pragma unroll
        for (int kk = 0; kk < 4; kk++) {
            const int kb = kk * 8;
            uint32_t af[2][4], bf[4][2];
            #pragma unroll
            for (int i = 0; i < 2; i++) {
                const int m0 = wm * 32 + i * 16;
                af[i][0] = __float_as_uint(As[m0 + grp    ][kb + t4    ]);
                af[i][1] = __float_as_uint(As[m0 + grp + 8][kb + t4    ]);
                af[i][2] = __float_as_uint(As[m0 + grp    ][kb + t4 + 4]);
                af[i][3] = __float_as_uint(As[m0 + grp + 8][kb + t4 + 4]);
            }
            #pragma unroll
            for (int j = 0; j < 4; j++) {
                const int n0 = wn * 32 + j * 8;
                bf[j][0] = __float_as_uint(Bs[n0 + grp][kb + t4    ]);
                bf[j][1] = __float_as_uint(Bs[n0 + grp][kb + t4 + 4]);
            }
            #pragma unroll
            for (int i = 0; i < 2; i++)
                #pragma unroll
                for (int j = 0; j < 4; j++)
                    mma_tf32(acc[i][j], af[i], bf[j]);
        }
        __syncthreads();
    }

    // epilogue: c0 (r0,c) c1 (r0,c+1) c2 (r0+8,c) c3 (r0+8,c+1), c = n0 + 2*t4
    #pragma unroll
    for (int i = 0; i < 2; i++) {
        const int r0 = brow + wm * 32 + i * 16 + grp;
        #pragma unroll
        for (int j = 0; j < 4; j++) {
            const int col = bcol + wn * 32 + j * 8 + 2 * t4;
            if (col >= N) continue;
            const float b0 = bias[col], b1 = bias[col + 1];
            #pragma unroll
            for (int half = 0; half < 2; half++) {
                const int r = r0 + half * 8;
                float v0 = acc[i][j][half * 2 + 0] + b0;
                float v1 = acc[i][j][half * 2 + 1] + b1;
                if (act == 1) { v0 = gelu_exact(v0); v1 = gelu_exact(v1); }
                if (res) {
                    const float2 rr = *(const float2*)&res[(size_t)r * N + col];
                    v0 += rr.x; v1 += rr.y;
                }
                *(float2*)&C[(size_t)r * N + col] = make_float2(v0, v1);
            }
        }
    }
}

// ------- deformable sampling (softmax fused), one token per block -----------
__global__ __launch_bounds__(128) void dcn_sample_kernel(
    const float* __restrict__ xp, const float* __restrict__ off,
    const float* __restrict__ logits, float* __restrict__ y)
{
    const int tok = blockIdx.x;
    const int n  = tok / (HH * WW);
    const int hw = tok % (HH * WW);
    const int h = hw / WW, w = hw % WW;
    const int g  = threadIdx.x >> 4;
    const int cc = threadIdx.x & 15;

    __shared__ float s_off[GG * KK * 2];   // 144
    __shared__ float s_msk[GG * KK];       // 72
    for (int i = threadIdx.x; i < GG * KK * 2; i += 128)
        s_off[i] = off[(size_t)tok * (GG * KK * 2) + i];
    for (int i = threadIdx.x; i < GG * KK; i += 128)
        s_msk[i] = logits[(size_t)tok * (GG * KK) + i];
    __syncthreads();

    // fused softmax over K per group (8 threads, serial K=9)
    if (threadIdx.x < GG) {
        float* p = s_msk + threadIdx.x * KK;
        float mx = -1e30f;
        #pragma unroll
        for (int k = 0; k < KK; k++) mx = fmaxf(mx, p[k]);
        float s = 0.0f;
        float e[KK];
        #pragma unroll
        for (int k = 0; k < KK; k++) { e[k] = __expf(p[k] - mx); s += e[k]; }
        const float inv = 1.0f / s;
        #pragma unroll
        for (int k = 0; k < KK; k++) p[k] = e[k] * inv;
    }
    __syncthreads();

    const float* base = xp + ((size_t)n * HH * WW) * CC + g * GC + cc;
    float acc = 0.0f;

    #pragma unroll
    for (int k = 0; k < KK; k++) {
        const float ox = s_off[(g * KK + k) * 2 + 0];
        const float oy = s_off[(g * KK + k) * 2 + 1];
        const float mw = s_msk[g * KK + k];
        const float px = (float)(w + 1 + (k / 3) - 1) + ox;
        const float py = (float)(h + 1 + (k % 3) - 1) + oy;
        const float x0f = floorf(px), y0f = floorf(py);
        const float tx = px - x0f, ty = py - y0f;
        const int x0 = (int)x0f, y0 = (int)y0f;

        float v00 = 0.f, v01 = 0.f, v10 = 0.f, v11 = 0.f;
        const bool yi0 = (y0 >= 1) & (y0 <= HH);
        const bool yi1 = (y0 + 1 >= 1) & (y0 + 1 <= HH);
        const bool xi0 = (x0 >= 1) & (x0 <= WW);
        const bool xi1 = (x0 + 1 >= 1) & (x0 + 1 <= WW);
        if (yi0 & xi0) v00 = base[((size_t)(y0 - 1) * WW + (x0 - 1)) * CC];
        if (yi0 & xi1) v01 = base[((size_t)(y0 - 1) * WW + (x0    )) * CC];
        if (yi1 & xi0) v10 = base[((size_t)(y0    ) * WW + (x0 - 1)) * CC];
        if (yi1 & xi1) v11 = base[((size_t)(y0    ) * WW + (x0    )) * CC];

        const float bl = (1.f - ty) * (1.f - tx) * v00 + (1.f - ty) * tx * v01
                       + ty * (1.f - tx) * v10 + ty * tx * v11;
        acc = fmaf(mw, bl, acc);
    }
    y[(size_t)tok * CC + g * GC + cc] = acc;
}

// ---------------------------------------------------------------------------
extern "C" void kernel_launch(void* const* d_in, const int* in_sizes, int n_in,
                              void* d_out, int out_size)
{
    const float* x      = (const float*)d_in[0];
    const float* ln1_g  = (const float*)d_in[1];
    const float* ln1_b  = (const float*)d_in[2];
    const float* in_w   = (const float*)d_in[3];
    const float* in_b   = (const float*)d_in[4];
    const float* dw_k   = (const float*)d_in[5];
    const float* dw_b   = (const float*)d_in[6];
    const float* dwln_g = (const float*)d_in[7];
    const float* dwln_b = (const float*)d_in[8];
    const float* off_w  = (const float*)d_in[9];
    const float* off_b  = (const float*)d_in[10];
    const float* mask_w = (const float*)d_in[11];
    const float* mask_b = (const float*)d_in[12];
    const float* out_w  = (const float*)d_in[13];
    const float* out_b  = (const float*)d_in[14];
    const float* ln2_g  = (const float*)d_in[15];
    const float* ln2_b  = (const float*)d_in[16];
    const float* fc1_w  = (const float*)d_in[17];
    const float* fc1_b  = (const float*)d_in[18];
    const float* fc2_w  = (const float*)d_in[19];
    const float* fc2_b  = (const float*)d_in[20];
    float* out = (float*)d_out;

    float *xn, *xp, *x1, *offp, *mskp, *yp, *x2, *hp, *h1;
    cudaGetSymbolAddress((void**)&xn,   g_xn);
    cudaGetSymbolAddress((void**)&xp,   g_xp);
    cudaGetSymbolAddress((void**)&x1,   g_x1);
    cudaGetSymbolAddress((void**)&offp, g_off);
    cudaGetSymbolAddress((void**)&mskp, g_msk);
    cudaGetSymbolAddress((void**)&yp,   g_y);
    cudaGetSymbolAddress((void**)&x2,   g_x2);
    cudaGetSymbolAddress((void**)&hp,   g_h);
    cudaGetSymbolAddress((void**)&h1,   g_h1);

    const int MROW = NTOK / 128;                 // 512
    const dim3 gemm128(2, MROW);                 // N=128
    const dim3 gemm144(3, MROW);                 // N=144 (guarded)
    const dim3 gemm72 (2, MROW);                 // N=72  (guarded)
    const dim3 gemm512(8, MROW);                 // N=512

    // 1. xn = LN1(x)
    ln_kernel<<<NTOK, 128>>>(x, ln1_g, ln1_b, xn);
    // 2. xp = xn @ in_w + in_b
    gemm_tf32_kernel<<<gemm128, 256>>>(xn, in_w, in_b, nullptr, xp, NTOK, CC, CC, 0);
    // 3. x1 = gelu(LN(dwconv(xn)))
    dwconv_ln_gelu_kernel<<<NTOK, 128>>>(xn, dw_k, dw_b, dwln_g, dwln_b, x1);
    // 4. offset = x1 @ off_w + off_b
    gemm_tf32_kernel<<<gemm144, 256>>>(x1, off_w, off_b, nullptr, offp, NTOK, GG * KK * 2, CC, 0);
    // 5. mask logits = x1 @ mask_w + mask_b  (softmax fused into sampler)
    gemm_tf32_kernel<<<gemm72, 256>>>(x1, mask_w, mask_b, nullptr, mskp, NTOK, GG * KK, CC, 0);
    // 6. y = deformable sample(xp, offset, softmax(logits))
    dcn_sample_kernel<<<NTOK, 128>>>(xp, offp, mskp, yp);
    // 7. x2 = y @ out_w + out_b + x
    gemm_tf32_kernel<<<gemm128, 256>>>(yp, out_w, out_b, x, x2, NTOK, CC, CC, 0);
    // 8. h = LN2(x2)
    ln_kernel<<<NTOK, 128>>>(x2, ln2_g, ln2_b, hp);
    // 9. h1 = gelu(h @ fc1_w + fc1_b)
    gemm_tf32_kernel<<<gemm512, 256>>>(hp, fc1_w, fc1_b, nullptr, h1, NTOK, HID, CC, 1);
    // 10. out = h1 @ fc2_w + fc2_b + x2
    gemm_tf32_kernel<<<gemm128, 256>>>(h1, fc2_w, fc2_b, x2, out, NTOK, CC, HID, 0);
}

// round 5
// speedup vs baseline: 3.5479x; 1.5837x over previous
#include <cuda_runtime.h>
#include <math.h>
#include <stdint.h>

#define NB   4
#define HH   128
#define WW   128
#define CC   128
#define GG   8
#define GC   16
#define KK   9
#define NTOK (NB * HH * WW)   // 65536
#define HID  512
#define NOM  256              // padded offset(144)+mask(72) combined width
#define EPS  1e-5f

// ---------------- scratch (device globals; no allocation allowed) ------------
__device__ float g_xn [NTOK * CC];
__device__ float g_xp [NTOK * CC];
__device__ float g_x1 [NTOK * CC];
__device__ float g_om [NTOK * NOM];      // combined offsets + mask logits
__device__ float g_y  [NTOK * CC];
__device__ float g_x2 [NTOK * CC];
__device__ float g_h  [NTOK * CC];
__device__ float g_h1 [NTOK * HID];
__device__ float g_wcat[CC * NOM];       // [K=128][256] packed off_w|mask_w|0
__device__ float g_bcat[NOM];

__device__ __forceinline__ float gelu_exact(float x) {
    return 0.5f * x * (1.0f + erff(x * 0.70710678118654752f));
}

__device__ __forceinline__ void mma_tf32(float c[4], const uint32_t a[4], const uint32_t b[2]) {
    asm volatile(
        "mma.sync.aligned.m16n8k8.row.col.f32.tf32.tf32.f32 "
        "{%0,%1,%2,%3}, {%4,%5,%6,%7}, {%8,%9}, {%0,%1,%2,%3};"
        : "+f"(c[0]), "+f"(c[1]), "+f"(c[2]), "+f"(c[3])
        : "r"(a[0]), "r"(a[1]), "r"(a[2]), "r"(a[3]), "r"(b[0]), "r"(b[1]));
}

__device__ __forceinline__ void cp_async16(uint32_t dst_smem, const void* src) {
    asm volatile("cp.async.cg.shared.global [%0], [%1], 16;" :: "r"(dst_smem), "l"(src));
}
__device__ __forceinline__ void cp_commit() { asm volatile("cp.async.commit_group;"); }
template <int N> __device__ __forceinline__ void cp_wait() {
    asm volatile("cp.async.wait_group %0;" :: "n"(N));
}

// ---------------- weight-packing prep: wcat = [off_w | mask_w | 0] ----------
__global__ __launch_bounds__(256) void prep_offmask_kernel(
    const float* __restrict__ off_w, const float* __restrict__ off_b,
    const float* __restrict__ mask_w, const float* __restrict__ mask_b,
    float* __restrict__ wcat, float* __restrict__ bcat)
{
    const int k = blockIdx.x;        // 0..127
    const int j = threadIdx.x;       // 0..255
    float v = 0.0f;
    if (j < 144)      v = off_w[k * 144 + j];
    else if (j < 216) v = mask_w[k * 72 + (j - 144)];
    wcat[k * NOM + j] = v;
    if (k == 0) {
        float bv = 0.0f;
        if (j < 144)      bv = off_b[j];
        else if (j < 216) bv = mask_b[j - 144];
        bcat[j] = bv;
    }
}

// ---------------- LayerNorm over C=128, one token per block -----------------
__global__ __launch_bounds__(128) void ln_kernel(
    const float* __restrict__ in, const float* __restrict__ g,
    const float* __restrict__ b, float* __restrict__ out)
{
    const int tok = blockIdx.x;
    const int c   = threadIdx.x;
    float v = in[(size_t)tok * CC + c];
    float s = v, s2 = v * v;
    #pragma unroll
    for (int o = 16; o > 0; o >>= 1) {
        s  += __shfl_xor_sync(0xffffffffu, s,  o);
        s2 += __shfl_xor_sync(0xffffffffu, s2, o);
    }
    __shared__ float ws[4], ws2[4];
    const int wid = c >> 5, lid = c & 31;
    if (lid == 0) { ws[wid] = s; ws2[wid] = s2; }
    __syncthreads();
    s  = ws[0] + ws[1] + ws[2] + ws[3];
    s2 = ws2[0] + ws2[1] + ws2[2] + ws2[3];
    const float mean = s * (1.0f / CC);
    const float var  = s2 * (1.0f / CC) - mean * mean;
    const float rstd = rsqrtf(var + EPS);
    out[(size_t)tok * CC + c] = (v - mean) * rstd * g[c] + b[c];
}

// ------- depthwise 3x3 conv (on xn) + bias, then LN + GELU, per token -------
__global__ __launch_bounds__(128) void dwconv_ln_gelu_kernel(
    const float* __restrict__ xn, const float* __restrict__ dwk,
    const float* __restrict__ dwb, const float* __restrict__ lg,
    const float* __restrict__ lb, float* __restrict__ out)
{
    const int tok = blockIdx.x;
    const int c   = threadIdx.x;
    const int n = tok / (HH * WW);
    const int hw = tok % (HH * WW);
    const int h = hw / WW, w = hw % WW;

    float acc = dwb[c];
    #pragma unroll
    for (int ky = 0; ky < 3; ky++) {
        const int yy = h + ky - 1;
        if (yy < 0 || yy >= HH) continue;
        #pragma unroll
        for (int kx = 0; kx < 3; kx++) {
            const int xx = w + kx - 1;
            if (xx < 0 || xx >= WW) continue;
            acc += xn[(((size_t)n * HH + yy) * WW + xx) * CC + c]
                 * dwk[(ky * 3 + kx) * CC + c];
        }
    }

    float s = acc, s2 = acc * acc;
    #pragma unroll
    for (int o = 16; o > 0; o >>= 1) {
        s  += __shfl_xor_sync(0xffffffffu, s,  o);
        s2 += __shfl_xor_sync(0xffffffffu, s2, o);
    }
    __shared__ float ws[4], ws2[4];
    const int wid = c >> 5, lid = c & 31;
    if (lid == 0) { ws[wid] = s; ws2[wid] = s2; }
    __syncthreads();
    s  = ws[0] + ws[1] + ws[2] + ws[3];
    s2 = ws2[0] + ws2[1] + ws2[2] + ws2[3];
    const float mean = s * (1.0f / CC);
    const float var  = s2 * (1.0f / CC) - mean * mean;
    const float rstd = rsqrtf(var + EPS);
    const float v = (acc - mean) * rstd * lg[c] + lb[c];
    out[(size_t)tok * CC + c] = gelu_exact(v);
}

// ---- tf32 GEMM, cp.async double-buffered: C = act(A@B + bias) [+ res] ------
// A: MxK row-major, B: KxN row-major. M%128==0, K%32==0, N%128==0.
// BM=128, BN=128, BK=32; 256 thr = 8 warps (2 M x 4 N), warp tile 64x32.
#define AS_STRIDE 36    // floats; a-frag bank = 4*grp + t4 (conflict-free)
#define BS_STRIDE 136   // floats; b-frag bank = 8*t4 + grp (conflict-free)
#define A_BUF (128 * AS_STRIDE)
#define B_BUF (32 * BS_STRIDE)
#define GEMM_SMEM_BYTES ((2 * A_BUF + 2 * B_BUF) * 4)

__global__ __launch_bounds__(256) void gemm_tf32_db_kernel(
    const float* __restrict__ A, const float* __restrict__ B,
    const float* __restrict__ bias, const float* __restrict__ res,
    float* __restrict__ C, int M, int N, int K, int act)
{
    extern __shared__ float smem[];
    float* sA = smem;                 // [2][128][AS_STRIDE]
    float* sB = smem + 2 * A_BUF;     // [2][32][BS_STRIDE]

    const int tid  = threadIdx.x;
    const int warp = tid >> 5;
    const int lane = tid & 31;
    const int grp  = lane >> 2;       // 0..7
    const int t4   = lane & 3;        // 0..3
    const int wm   = warp >> 2;       // 0..1 -> 64 rows
    const int wn   = warp & 3;        // 0..3 -> 32 cols
    const int brow = blockIdx.y * 128;
    const int bcol = blockIdx.x * 128;

    const uint32_t sA_u = (uint32_t)__cvta_generic_to_shared(sA);
    const uint32_t sB_u = (uint32_t)__cvta_generic_to_shared(sB);

    // A tile: 128 rows x 32 floats = 1024 x 16B chunks, 4 per thread
    const int ar = tid >> 1;              // row 0..127 (2 chunks side by side? no)
    // use: idx = it*256 + tid; r = idx>>3, c = idx&7
    // B tile: 32 rows x 128 floats = 1024 chunks as well
    const int KT = K >> 5;

    auto load_tile = [&](int kt, int buf) {
        const int k0 = kt << 5;
        #pragma unroll
        for (int it = 0; it < 4; it++) {
            const int idx = it * 256 + tid;
            const int r = idx >> 3, c = idx & 7;
            cp_async16(sA_u + (buf * A_BUF + r * AS_STRIDE + c * 4) * 4,
                       &A[(size_t)(brow + r) * K + k0 + c * 4]);
        }
        #pragma unroll
        for (int it = 0; it < 4; it++) {
            const int idx = it * 256 + tid;
            const int kr = idx >> 5, c = idx & 31;
            cp_async16(sB_u + (buf * B_BUF + kr * BS_STRIDE + c * 4) * 4,
                       &B[(size_t)(k0 + kr) * N + bcol + c * 4]);
        }
        cp_commit();
    };

    float acc[4][4][4];
    #pragma unroll
    for (int i = 0; i < 4; i++)
        #pragma unroll
        for (int j = 0; j < 4; j++)
            #pragma unroll
            for (int q = 0; q < 4; q++) acc[i][j][q] = 0.0f;

    load_tile(0, 0);

    for (int kt = 0; kt < KT; kt++) {
        if (kt + 1 < KT) { load_tile(kt + 1, (kt + 1) & 1); cp_wait<1>(); }
        else             { cp_wait<0>(); }
        __syncthreads();

        const float* Ab = sA + (kt & 1) * A_BUF;
        const float* Bb = sB + (kt & 1) * B_BUF;

        #pragma unroll
        for (int kk = 0; kk < 4; kk++) {
            const int kb = kk * 8;
            uint32_t af[4][4], bf[4][2];
            #pragma unroll
            for (int i = 0; i < 4; i++) {
                const int m0 = wm * 64 + i * 16 + grp;
                af[i][0] = __float_as_uint(Ab[(m0    ) * AS_STRIDE + kb + t4    ]);
                af[i][1] = __float_as_uint(Ab[(m0 + 8) * AS_STRIDE + kb + t4    ]);
                af[i][2] = __float_as_uint(Ab[(m0    ) * AS_STRIDE + kb + t4 + 4]);
                af[i][3] = __float_as_uint(Ab[(m0 + 8) * AS_STRIDE + kb + t4 + 4]);
            }
            #pragma unroll
            for (int j = 0; j < 4; j++) {
                const int n0 = wn * 32 + j * 8 + grp;
                bf[j][0] = __float_as_uint(Bb[(kb + t4    ) * BS_STRIDE + n0]);
                bf[j][1] = __float_as_uint(Bb[(kb + t4 + 4) * BS_STRIDE + n0]);
            }
            #pragma unroll
            for (int i = 0; i < 4; i++)
                #pragma unroll
                for (int j = 0; j < 4; j++)
                    mma_tf32(acc[i][j], af[i], bf[j]);
        }
        __syncthreads();
    }

    // epilogue: thread owns (r0=grp+half*8, col=2*t4 {,+1}) per mma tile
    #pragma unroll
    for (int i = 0; i < 4; i++) {
        const int r0 = brow + wm * 64 + i * 16 + grp;
        #pragma unroll
        for (int j = 0; j < 4; j++) {
            const int col = bcol + wn * 32 + j * 8 + 2 * t4;
            const float b0 = bias[col], b1 = bias[col + 1];
            #pragma unroll
            for (int half = 0; half < 2; half++) {
                const int r = r0 + half * 8;
                float v0 = acc[i][j][half * 2 + 0] + b0;
                float v1 = acc[i][j][half * 2 + 1] + b1;
                if (act == 1) { v0 = gelu_exact(v0); v1 = gelu_exact(v1); }
                if (res) {
                    const float2 rr = *(const float2*)&res[(size_t)r * N + col];
                    v0 += rr.x; v1 += rr.y;
                }
                *(float2*)&C[(size_t)r * N + col] = make_float2(v0, v1);
            }
        }
    }
}

// ------- deformable sampling + fused softmax; 1 warp per token, float4 ------
__global__ __launch_bounds__(128) void dcn_sample_kernel(
    const float* __restrict__ xp, const float* __restrict__ om,
    float* __restrict__ y)
{
    const int tt   = threadIdx.x >> 5;         // 0..3 token within block
    const int lane = threadIdx.x & 31;
    const int tok  = blockIdx.x * 4 + tt;
    const int n  = tok / (HH * WW);
    const int hw = tok % (HH * WW);
    const int h = hw / WW, w = hw % WW;

    __shared__ float s_om[4][216];             // [tt][144 off | 72 msk]
    const float* src = om + (size_t)tok * NOM;
    for (int i = lane; i < 216; i += 32) s_om[tt][i] = src[i];
    __syncwarp();

    // softmax over K per group: lanes 0..7
    if (lane < GG) {
        float* p = &s_om[tt][144 + lane * KK];
        float mx = -1e30f;
        #pragma unroll
        for (int k = 0; k < KK; k++) mx = fmaxf(mx, p[k]);
        float s = 0.0f, e[KK];
        #pragma unroll
        for (int k = 0; k < KK; k++) { e[k] = __expf(p[k] - mx); s += e[k]; }
        const float inv = 1.0f / s;
        #pragma unroll
        for (int k = 0; k < KK; k++) p[k] = e[k] * inv;
    }
    __syncwarp();

    const int g  = lane >> 2;                  // 0..7
    const int c4 = lane & 3;                   // channel quad
    const float* base = xp + ((size_t)n * HH * WW) * CC + g * GC + c4 * 4;
    float4 acc = make_float4(0.f, 0.f, 0.f, 0.f);

    #pragma unroll
    for (int k = 0; k < KK; k++) {
        const float ox = s_om[tt][(g * KK + k) * 2 + 0];
        const float oy = s_om[tt][(g * KK + k) * 2 + 1];
        const float mw = s_om[tt][144 + g * KK + k];
        const float px = (float)(w + 1 + (k / 3) - 1) + ox;
        const float py = (float)(h + 1 + (k % 3) - 1) + oy;
        const float x0f = floorf(px), y0f = floorf(py);
        const float tx = px - x0f, ty = py - y0f;
        const int x0 = (int)x0f, y0 = (int)y0f;

        const bool yi0 = (y0 >= 1) & (y0 <= HH);
        const bool yi1 = (y0 + 1 >= 1) & (y0 + 1 <= HH);
        const bool xi0 = (x0 >= 1) & (x0 <= WW);
        const bool xi1 = (x0 + 1 >= 1) & (x0 + 1 <= WW);

        float4 v00 = make_float4(0,0,0,0), v01 = v00, v10 = v00, v11 = v00;
        if (yi0 & xi0) v00 = *(const float4*)&base[((size_t)(y0 - 1) * WW + (x0 - 1)) * CC];
        if (yi0 & xi1) v01 = *(const float4*)&base[((size_t)(y0 - 1) * WW + (x0    )) * CC];
        if (yi1 & xi0) v10 = *(const float4*)&base[((size_t)(y0    ) * WW + (x0 - 1)) * CC];
        if (yi1 & xi1) v11 = *(const float4*)&base[((size_t)(y0    ) * WW + (x0    )) * CC];

        const float w00 = mw * (1.f - ty) * (1.f - tx);
        const float w01 = mw * (1.f - ty) * tx;
        const float w10 = mw * ty * (1.f - tx);
        const float w11 = mw * ty * tx;
        acc.x += w00 * v00.x + w01 * v01.x + w10 * v10.x + w11 * v11.x;
        acc.y += w00 * v00.y + w01 * v01.y + w10 * v10.y + w11 * v11.y;
        acc.z += w00 * v00.z + w01 * v01.z + w10 * v10.z + w11 * v11.z;
        acc.w += w00 * v00.w + w01 * v01.w + w10 * v10.w + w11 * v11.w;
    }
    *(float4*)&y[(size_t)tok * CC + g * GC + c4 * 4] = acc;
}

// ---------------------------------------------------------------------------
extern "C" void kernel_launch(void* const* d_in, const int* in_sizes, int n_in,
                              void* d_out, int out_size)
{
    const float* x      = (const float*)d_in[0];
    const float* ln1_g  = (const float*)d_in[1];
    const float* ln1_b  = (const float*)d_in[2];
    const float* in_w   = (const float*)d_in[3];
    const float* in_b   = (const float*)d_in[4];
    const float* dw_k   = (const float*)d_in[5];
    const float* dw_b   = (const float*)d_in[6];
    const float* dwln_g = (const float*)d_in[7];
    const float* dwln_b = (const float*)d_in[8];
    const float* off_w  = (const float*)d_in[9];
    const float* off_b  = (const float*)d_in[10];
    const float* mask_w = (const float*)d_in[11];
    const float* mask_b = (const float*)d_in[12];
    const float* out_w  = (const float*)d_in[13];
    const float* out_b  = (const float*)d_in[14];
    const float* ln2_g  = (const float*)d_in[15];
    const float* ln2_b  = (const float*)d_in[16];
    const float* fc1_w  = (const float*)d_in[17];
    const float* fc1_b  = (const float*)d_in[18];
    const float* fc2_w  = (const float*)d_in[19];
    const float* fc2_b  = (const float*)d_in[20];
    float* out = (float*)d_out;

    float *xn, *xp, *x1, *omp, *yp, *x2, *hp, *h1, *wcat, *bcat;
    cudaGetSymbolAddress((void**)&xn,   g_xn);
    cudaGetSymbolAddress((void**)&xp,   g_xp);
    cudaGetSymbolAddress((void**)&x1,   g_x1);
    cudaGetSymbolAddress((void**)&omp,  g_om);
    cudaGetSymbolAddress((void**)&yp,   g_y);
    cudaGetSymbolAddress((void**)&x2,   g_x2);
    cudaGetSymbolAddress((void**)&hp,   g_h);
    cudaGetSymbolAddress((void**)&h1,   g_h1);
    cudaGetSymbolAddress((void**)&wcat, g_wcat);
    cudaGetSymbolAddress((void**)&bcat, g_bcat);

    static bool attr_done = false;
    if (!attr_done) {
        cudaFuncSetAttribute(gemm_tf32_db_kernel,
                             cudaFuncAttributeMaxDynamicSharedMemorySize,
                             GEMM_SMEM_BYTES);
        attr_done = true;
    }

    const int MROW = NTOK / 128;                 // 512
    const dim3 gemm128(1, MROW);
    const dim3 gemm256(2, MROW);
    const dim3 gemm512(4, MROW);

    // 0. pack offset|mask weights (idempotent)
    prep_offmask_kernel<<<CC, NOM>>>(off_w, off_b, mask_w, mask_b, wcat, bcat);
    // 1. xn = LN1(x)
    ln_kernel<<<NTOK, 128>>>(x, ln1_g, ln1_b, xn);
    // 2. xp = xn @ in_w + in_b
    gemm_tf32_db_kernel<<<gemm128, 256, GEMM_SMEM_BYTES>>>(xn, in_w, in_b, nullptr, xp, NTOK, CC, CC, 0);
    // 3. x1 = gelu(LN(dwconv(xn)))
    dwconv_ln_gelu_kernel<<<NTOK, 128>>>(xn, dw_k, dw_b, dwln_g, dwln_b, x1);
    // 4. [offset | mask logits] = x1 @ wcat + bcat
    gemm_tf32_db_kernel<<<gemm256, 256, GEMM_SMEM_BYTES>>>(x1, wcat, bcat, nullptr, omp, NTOK, NOM, CC, 0);
    // 5. y = deformable sample(xp, offsets, softmax(logits))
    dcn_sample_kernel<<<NTOK / 4, 128>>>(xp, omp, yp);
    // 6. x2 = y @ out_w + out_b + x
    gemm_tf32_db_kernel<<<gemm128, 256, GEMM_SMEM_BYTES>>>(yp, out_w, out_b, x, x2, NTOK, CC, CC, 0);
    // 7. h = LN2(x2)
    ln_kernel<<<NTOK, 128>>>(x2, ln2_g, ln2_b, hp);
    // 8. h1 = gelu(h @ fc1_w + fc1_b)
    gemm_tf32_db_kernel<<<gemm512, 256, GEMM_SMEM_BYTES>>>(hp, fc1_w, fc1_b, nullptr, h1, NTOK, HID, CC, 1);
    // 9. out = h1 @ fc2_w + fc2_b + x2
    gemm_tf32_db_kernel<<<gemm128, 256, GEMM_SMEM_BYTES>>>(h1, fc2_w, fc2_b, x2, out, NTOK, CC, HID, 0);
}

// round 6
// speedup vs baseline: 4.2747x; 1.2048x over previous
#include <cuda_runtime.h>
#include <math.h>
#include <stdint.h>

#define NB   4
#define HH   128
#define WW   128
#define CC   128
#define GG   8
#define GC   16
#define KK   9
#define NTOK (NB * HH * WW)   // 65536
#define HID  512
#define NOM  256              // padded offset(144)+mask(72) combined width
#define EPS  1e-5f

// ---------------- scratch (device globals; no allocation allowed) ------------
__device__ float g_xn [NTOK * CC];
__device__ float g_xp [NTOK * CC];
__device__ float g_x1 [NTOK * CC];
__device__ float g_om [NTOK * NOM];      // combined offsets + mask logits
__device__ float g_y  [NTOK * CC];
__device__ float g_x2 [NTOK * CC];
__device__ float g_h  [NTOK * CC];
__device__ float g_h1 [NTOK * HID];
__device__ float g_wcat[CC * NOM];       // [K=128][256] packed off_w|mask_w|0
__device__ float g_bcat[NOM];

__device__ __forceinline__ float gelu_exact(float x) {
    return 0.5f * x * (1.0f + erff(x * 0.70710678118654752f));
}

__device__ __forceinline__ void mma_tf32(float c[4], const uint32_t a[4], const uint32_t b[2]) {
    asm volatile(
        "mma.sync.aligned.m16n8k8.row.col.f32.tf32.tf32.f32 "
        "{%0,%1,%2,%3}, {%4,%5,%6,%7}, {%8,%9}, {%0,%1,%2,%3};"
        : "+f"(c[0]), "+f"(c[1]), "+f"(c[2]), "+f"(c[3])
        : "r"(a[0]), "r"(a[1]), "r"(a[2]), "r"(a[3]), "r"(b[0]), "r"(b[1]));
}

__device__ __forceinline__ void cp_async16(uint32_t dst_smem, const void* src) {
    asm volatile("cp.async.cg.shared.global [%0], [%1], 16;" :: "r"(dst_smem), "l"(src));
}
__device__ __forceinline__ void cp_commit() { asm volatile("cp.async.commit_group;"); }
template <int N> __device__ __forceinline__ void cp_wait() {
    asm volatile("cp.async.wait_group %0;" :: "n"(N));
}

// ---------------- weight-packing prep: wcat = [off_w | mask_w | 0] ----------
__global__ __launch_bounds__(256) void prep_offmask_kernel(
    const float* __restrict__ off_w, const float* __restrict__ off_b,
    const float* __restrict__ mask_w, const float* __restrict__ mask_b,
    float* __restrict__ wcat, float* __restrict__ bcat)
{
    const int k = blockIdx.x;
    const int j = threadIdx.x;
    float v = 0.0f;
    if (j < 144)      v = off_w[k * 144 + j];
    else if (j < 216) v = mask_w[k * 72 + (j - 144)];
    wcat[k * NOM + j] = v;
    if (k == 0) {
        float bv = 0.0f;
        if (j < 144)      bv = off_b[j];
        else if (j < 216) bv = mask_b[j - 144];
        bcat[j] = bv;
    }
}

// -------- LayerNorm, warp per token, float4, shfl-only reduction ------------
// grid = NTOK/8, block = 256 (8 warps = 8 tokens)
__global__ __launch_bounds__(256) void ln_v4_kernel(
    const float* __restrict__ in, const float* __restrict__ g,
    const float* __restrict__ b, float* __restrict__ out)
{
    const int warp = threadIdx.x >> 5;
    const int lane = threadIdx.x & 31;
    const int tok  = blockIdx.x * 8 + warp;

    const float4 v = *(const float4*)&in[(size_t)tok * CC + lane * 4];
    float s  = v.x + v.y + v.z + v.w;
    float s2 = v.x * v.x + v.y * v.y + v.z * v.z + v.w * v.w;
    #pragma unroll
    for (int o = 16; o > 0; o >>= 1) {
        s  += __shfl_xor_sync(0xffffffffu, s,  o);
        s2 += __shfl_xor_sync(0xffffffffu, s2, o);
    }
    const float mean = s * (1.0f / CC);
    const float var  = s2 * (1.0f / CC) - mean * mean;
    const float rstd = rsqrtf(var + EPS);
    const float4 gg = *(const float4*)&g[lane * 4];
    const float4 bb = *(const float4*)&b[lane * 4];
    float4 o4;
    o4.x = (v.x - mean) * rstd * gg.x + bb.x;
    o4.y = (v.y - mean) * rstd * gg.y + bb.y;
    o4.z = (v.z - mean) * rstd * gg.z + bb.z;
    o4.w = (v.w - mean) * rstd * gg.w + bb.w;
    *(float4*)&out[(size_t)tok * CC + lane * 4] = o4;
}

// ------ dwconv3x3 + LN + GELU: warp per token, float4, interior fast path ---
// grid = NTOK/8, block = 256
__global__ __launch_bounds__(256) void dwconv_ln_gelu_v4_kernel(
    const float* __restrict__ xn, const float* __restrict__ dwk,
    const float* __restrict__ dwb, const float* __restrict__ lg,
    const float* __restrict__ lb, float* __restrict__ out)
{
    const int warp = threadIdx.x >> 5;
    const int lane = threadIdx.x & 31;
    const int tok  = blockIdx.x * 8 + warp;
    const int hw = tok & (HH * WW - 1);
    const int h = hw >> 7, w = hw & 127;
    const int c4 = lane * 4;

    const float4 bia = *(const float4*)&dwb[c4];
    float4 acc = bia;

    const float* p = xn + (size_t)tok * CC + c4;   // center
    const float* kw = dwk + c4;

    if (h >= 1 && h <= HH - 2 && w >= 1 && w <= WW - 2) {
        // interior: constant offsets, fully unrolled
        #pragma unroll
        for (int ky = 0; ky < 3; ky++) {
            #pragma unroll
            for (int kx = 0; kx < 3; kx++) {
                const int doff = ((ky - 1) * WW + (kx - 1)) * CC;
                const float4 v = *(const float4*)(p + doff);
                const float4 k = *(const float4*)(kw + (ky * 3 + kx) * CC);
                acc.x = fmaf(v.x, k.x, acc.x);
                acc.y = fmaf(v.y, k.y, acc.y);
                acc.z = fmaf(v.z, k.z, acc.z);
                acc.w = fmaf(v.w, k.w, acc.w);
            }
        }
    } else {
        #pragma unroll
        for (int ky = 0; ky < 3; ky++) {
            const int yy = h + ky - 1;
            if (yy < 0 || yy >= HH) continue;
            #pragma unroll
            for (int kx = 0; kx < 3; kx++) {
                const int xx = w + kx - 1;
                if (xx < 0 || xx >= WW) continue;
                const int doff = ((ky - 1) * WW + (kx - 1)) * CC;
                const float4 v = *(const float4*)(p + doff);
                const float4 k = *(const float4*)(kw + (ky * 3 + kx) * CC);
                acc.x = fmaf(v.x, k.x, acc.x);
                acc.y = fmaf(v.y, k.y, acc.y);
                acc.z = fmaf(v.z, k.z, acc.z);
                acc.w = fmaf(v.w, k.w, acc.w);
            }
        }
    }

    // LN over the 128 channels of this warp's token
    float s  = acc.x + acc.y + acc.z + acc.w;
    float s2 = acc.x * acc.x + acc.y * acc.y + acc.z * acc.z + acc.w * acc.w;
    #pragma unroll
    for (int o = 16; o > 0; o >>= 1) {
        s  += __shfl_xor_sync(0xffffffffu, s,  o);
        s2 += __shfl_xor_sync(0xffffffffu, s2, o);
    }
    const float mean = s * (1.0f / CC);
    const float var  = s2 * (1.0f / CC) - mean * mean;
    const float rstd = rsqrtf(var + EPS);
    const float4 gg = *(const float4*)&lg[c4];
    const float4 bb = *(const float4*)&lb[c4];
    float4 o4;
    o4.x = gelu_exact((acc.x - mean) * rstd * gg.x + bb.x);
    o4.y = gelu_exact((acc.y - mean) * rstd * gg.y + bb.y);
    o4.z = gelu_exact((acc.z - mean) * rstd * gg.z + bb.z);
    o4.w = gelu_exact((acc.w - mean) * rstd * gg.w + bb.w);
    *(float4*)&out[(size_t)tok * CC + c4] = o4;
}

// ---- tf32 GEMM, cp.async double-buffered: C = act(A@B + bias) [+ res] ------
// BM=128, BN=128, BK=32; 256 thr = 8 warps (2 M x 4 N), warp tile 64x32.
#define AS_STRIDE 36
#define BS_STRIDE 136
#define A_BUF (128 * AS_STRIDE)
#define B_BUF (32 * BS_STRIDE)
#define GEMM_SMEM_BYTES ((2 * A_BUF + 2 * B_BUF) * 4)

__global__ __launch_bounds__(256) void gemm_tf32_db_kernel(
    const float* __restrict__ A, const float* __restrict__ B,
    const float* __restrict__ bias, const float* __restrict__ res,
    float* __restrict__ C, int M, int N, int K, int act)
{
    extern __shared__ float smem[];
    float* sA = smem;
    float* sB = smem + 2 * A_BUF;

    const int tid  = threadIdx.x;
    const int warp = tid >> 5;
    const int lane = tid & 31;
    const int grp  = lane >> 2;
    const int t4   = lane & 3;
    const int wm   = warp >> 2;
    const int wn   = warp & 3;
    const int brow = blockIdx.y * 128;
    const int bcol = blockIdx.x * 128;

    const uint32_t sA_u = (uint32_t)__cvta_generic_to_shared(sA);
    const uint32_t sB_u = (uint32_t)__cvta_generic_to_shared(sB);
    const int KT = K >> 5;

    auto load_tile = [&](int kt, int buf) {
        const int k0 = kt << 5;
        #pragma unroll
        for (int it = 0; it < 4; it++) {
            const int idx = it * 256 + tid;
            const int r = idx >> 3, c = idx & 7;
            cp_async16(sA_u + (buf * A_BUF + r * AS_STRIDE + c * 4) * 4,
                       &A[(size_t)(brow + r) * K + k0 + c * 4]);
        }
        #pragma unroll
        for (int it = 0; it < 4; it++) {
            const int idx = it * 256 + tid;
            const int kr = idx >> 5, c = idx & 31;
            cp_async16(sB_u + (buf * B_BUF + kr * BS_STRIDE + c * 4) * 4,
                       &B[(size_t)(k0 + kr) * N + bcol + c * 4]);
        }
        cp_commit();
    };

    float acc[4][4][4];
    #pragma unroll
    for (int i = 0; i < 4; i++)
        #pragma unroll
        for (int j = 0; j < 4; j++)
            #pragma unroll
            for (int q = 0; q < 4; q++) acc[i][j][q] = 0.0f;

    load_tile(0, 0);

    for (int kt = 0; kt < KT; kt++) {
        if (kt + 1 < KT) { load_tile(kt + 1, (kt + 1) & 1); cp_wait<1>(); }
        else             { cp_wait<0>(); }
        __syncthreads();

        const float* Ab = sA + (kt & 1) * A_BUF;
        const float* Bb = sB + (kt & 1) * B_BUF;

        #pragma unroll
        for (int kk = 0; kk < 4; kk++) {
            const int kb = kk * 8;
            uint32_t af[4][4], bf[4][2];
            #pragma unroll
            for (int i = 0; i < 4; i++) {
                const int m0 = wm * 64 + i * 16 + grp;
                af[i][0] = __float_as_uint(Ab[(m0    ) * AS_STRIDE + kb + t4    ]);
                af[i][1] = __float_as_uint(Ab[(m0 + 8) * AS_STRIDE + kb + t4    ]);
                af[i][2] = __float_as_uint(Ab[(m0    ) * AS_STRIDE + kb + t4 + 4]);
                af[i][3] = __float_as_uint(Ab[(m0 + 8) * AS_STRIDE + kb + t4 + 4]);
            }
            #pragma unroll
            for (int j = 0; j < 4; j++) {
                const int n0 = wn * 32 + j * 8 + grp;
                bf[j][0] = __float_as_uint(Bb[(kb + t4    ) * BS_STRIDE + n0]);
                bf[j][1] = __float_as_uint(Bb[(kb + t4 + 4) * BS_STRIDE + n0]);
            }
            #pragma unroll
            for (int i = 0; i < 4; i++)
                #pragma unroll
                for (int j = 0; j < 4; j++)
                    mma_tf32(acc[i][j], af[i], bf[j]);
        }
        __syncthreads();
    }

    #pragma unroll
    for (int i = 0; i < 4; i++) {
        const int r0 = brow + wm * 64 + i * 16 + grp;
        #pragma unroll
        for (int j = 0; j < 4; j++) {
            const int col = bcol + wn * 32 + j * 8 + 2 * t4;
            const float b0 = bias[col], b1 = bias[col + 1];
            #pragma unroll
            for (int half = 0; half < 2; half++) {
                const int r = r0 + half * 8;
                float v0 = acc[i][j][half * 2 + 0] + b0;
                float v1 = acc[i][j][half * 2 + 1] + b1;
                if (act == 1) { v0 = gelu_exact(v0); v1 = gelu_exact(v1); }
                if (res) {
                    const float2 rr = *(const float2*)&res[(size_t)r * N + col];
                    v0 += rr.x; v1 += rr.y;
                }
                *(float2*)&C[(size_t)r * N + col] = make_float2(v0, v1);
            }
        }
    }
}

// ------- deformable sampling + fused softmax; 1 warp per token, float4 ------
__global__ __launch_bounds__(128) void dcn_sample_kernel(
    const float* __restrict__ xp, const float* __restrict__ om,
    float* __restrict__ y)
{
    const int tt   = threadIdx.x >> 5;
    const int lane = threadIdx.x & 31;
    const int tok  = blockIdx.x * 4 + tt;
    const int n  = tok / (HH * WW);
    const int hw = tok % (HH * WW);
    const int h = hw / WW, w = hw % WW;

    __shared__ float s_om[4][216];
    const float* src = om + (size_t)tok * NOM;
    for (int i = lane; i < 216; i += 32) s_om[tt][i] = src[i];
    __syncwarp();

    if (lane < GG) {
        float* p = &s_om[tt][144 + lane * KK];
        float mx = -1e30f;
        #pragma unroll
        for (int k = 0; k < KK; k++) mx = fmaxf(mx, p[k]);
        float s = 0.0f, e[KK];
        #pragma unroll
        for (int k = 0; k < KK; k++) { e[k] = __expf(p[k] - mx); s += e[k]; }
        const float inv = 1.0f / s;
        #pragma unroll
        for (int k = 0; k < KK; k++) p[k] = e[k] * inv;
    }
    __syncwarp();

    const int g  = lane >> 2;
    const int c4 = lane & 3;
    const float* base = xp + ((size_t)n * HH * WW) * CC + g * GC + c4 * 4;
    float4 acc = make_float4(0.f, 0.f, 0.f, 0.f);

    #pragma unroll
    for (int k = 0; k < KK; k++) {
        const float ox = s_om[tt][(g * KK + k) * 2 + 0];
        const float oy = s_om[tt][(g * KK + k) * 2 + 1];
        const float mw = s_om[tt][144 + g * KK + k];
        const float px = (float)(w + 1 + (k / 3) - 1) + ox;
        const float py = (float)(h + 1 + (k % 3) - 1) + oy;
        const float x0f = floorf(px), y0f = floorf(py);
        const float tx = px - x0f, ty = py - y0f;
        const int x0 = (int)x0f, y0 = (int)y0f;

        const bool yi0 = (y0 >= 1) & (y0 <= HH);
        const bool yi1 = (y0 + 1 >= 1) & (y0 + 1 <= HH);
        const bool xi0 = (x0 >= 1) & (x0 <= WW);
        const bool xi1 = (x0 + 1 >= 1) & (x0 + 1 <= WW);

        float4 v00 = make_float4(0,0,0,0), v01 = v00, v10 = v00, v11 = v00;
        if (yi0 & xi0) v00 = *(const float4*)&base[((size_t)(y0 - 1) * WW + (x0 - 1)) * CC];
        if (yi0 & xi1) v01 = *(const float4*)&base[((size_t)(y0 - 1) * WW + (x0    )) * CC];
        if (yi1 & xi0) v10 = *(const float4*)&base[((size_t)(y0    ) * WW + (x0 - 1)) * CC];
        if (yi1 & xi1) v11 = *(const float4*)&base[((size_t)(y0    ) * WW + (x0    )) * CC];

        const float w00 = mw * (1.f - ty) * (1.f - tx);
        const float w01 = mw * (1.f - ty) * tx;
        const float w10 = mw * ty * (1.f - tx);
        const float w11 = mw * ty * tx;
        acc.x += w00 * v00.x + w01 * v01.x + w10 * v10.x + w11 * v11.x;
        acc.y += w00 * v00.y + w01 * v01.y + w10 * v10.y + w11 * v11.y;
        acc.z += w00 * v00.z + w01 * v01.z + w10 * v10.z + w11 * v11.z;
        acc.w += w00 * v00.w + w01 * v01.w + w10 * v10.w + w11 * v11.w;
    }
    *(float4*)&y[(size_t)tok * CC + g * GC + c4 * 4] = acc;
}

// ---------------------------------------------------------------------------
extern "C" void kernel_launch(void* const* d_in, const int* in_sizes, int n_in,
                              void* d_out, int out_size)
{
    const float* x      = (const float*)d_in[0];
    const float* ln1_g  = (const float*)d_in[1];
    const float* ln1_b  = (const float*)d_in[2];
    const float* in_w   = (const float*)d_in[3];
    const float* in_b   = (const float*)d_in[4];
    const float* dw_k   = (const float*)d_in[5];
    const float* dw_b   = (const float*)d_in[6];
    const float* dwln_g = (const float*)d_in[7];
    const float* dwln_b = (const float*)d_in[8];
    const float* off_w  = (const float*)d_in[9];
    const float* off_b  = (const float*)d_in[10];
    const float* mask_w = (const float*)d_in[11];
    const float* mask_b = (const float*)d_in[12];
    const float* out_w  = (const float*)d_in[13];
    const float* out_b  = (const float*)d_in[14];
    const float* ln2_g  = (const float*)d_in[15];
    const float* ln2_b  = (const float*)d_in[16];
    const float* fc1_w  = (const float*)d_in[17];
    const float* fc1_b  = (const float*)d_in[18];
    const float* fc2_w  = (const float*)d_in[19];
    const float* fc2_b  = (const float*)d_in[20];
    float* out = (float*)d_out;

    float *xn, *xp, *x1, *omp, *yp, *x2, *hp, *h1, *wcat, *bcat;
    cudaGetSymbolAddress((void**)&xn,   g_xn);
    cudaGetSymbolAddress((void**)&xp,   g_xp);
    cudaGetSymbolAddress((void**)&x1,   g_x1);
    cudaGetSymbolAddress((void**)&omp,  g_om);
    cudaGetSymbolAddress((void**)&yp,   g_y);
    cudaGetSymbolAddress((void**)&x2,   g_x2);
    cudaGetSymbolAddress((void**)&hp,   g_h);
    cudaGetSymbolAddress((void**)&h1,   g_h1);
    cudaGetSymbolAddress((void**)&wcat, g_wcat);
    cudaGetSymbolAddress((void**)&bcat, g_bcat);

    static bool attr_done = false;
    if (!attr_done) {
        cudaFuncSetAttribute(gemm_tf32_db_kernel,
                             cudaFuncAttributeMaxDynamicSharedMemorySize,
                             GEMM_SMEM_BYTES);
        attr_done = true;
    }

    const int MROW = NTOK / 128;
    const dim3 gemm128(1, MROW);
    const dim3 gemm256(2, MROW);
    const dim3 gemm512(4, MROW);

    prep_offmask_kernel<<<CC, NOM>>>(off_w, off_b, mask_w, mask_b, wcat, bcat);
    ln_v4_kernel<<<NTOK / 8, 256>>>(x, ln1_g, ln1_b, xn);
    gemm_tf32_db_kernel<<<gemm128, 256, GEMM_SMEM_BYTES>>>(xn, in_w, in_b, nullptr, xp, NTOK, CC, CC, 0);
    dwconv_ln_gelu_v4_kernel<<<NTOK / 8, 256>>>(xn, dw_k, dw_b, dwln_g, dwln_b, x1);
    gemm_tf32_db_kernel<<<gemm256, 256, GEMM_SMEM_BYTES>>>(x1, wcat, bcat, nullptr, omp, NTOK, NOM, CC, 0);
    dcn_sample_kernel<<<NTOK / 4, 128>>>(xp, omp, yp);
    gemm_tf32_db_kernel<<<gemm128, 256, GEMM_SMEM_BYTES>>>(yp, out_w, out_b, x, x2, NTOK, CC, CC, 0);
    ln_v4_kernel<<<NTOK / 8, 256>>>(x2, ln2_g, ln2_b, hp);
    gemm_tf32_db_kernel<<<gemm512, 256, GEMM_SMEM_BYTES>>>(hp, fc1_w, fc1_b, nullptr, h1, NTOK, HID, CC, 1);
    gemm_tf32_db_kernel<<<gemm128, 256, GEMM_SMEM_BYTES>>>(h1, fc2_w, fc2_b, x2, out, NTOK, CC, HID, 0);
}